// round 2
// baseline (speedup 1.0000x reference)
#include <cuda_runtime.h>

// loss = mean_b( ||sum_n att_n||^2 - sum_n ||att_n||^2 ),  att_n = x_n / max(||x_n||, 1e-12)
// B=128, N=64, D=2048. One block per batch; fused cross-batch reduction via
// last-block ticket (deterministic fixed-order final sum, self-resetting counter).

#define B_BATCH 128
#define N_ROWS  64
#define D_COLS  2048          // 512 float4
#define NWARP   16
#define NTHREADS 512
#define EPSF    1e-12f

static __device__ double g_batch_loss[B_BATCH];
static __device__ unsigned int g_done = 0;

__global__ void __launch_bounds__(NTHREADS, 1)
loss_fused_kernel(const float* __restrict__ in, float* __restrict__ out)
{
    __shared__ float4 sbuf[NWARP][128];   // 32 KB, column-chunk publish area
    __shared__ double dred[2 * NWARP];
    __shared__ unsigned int s_ticket;

    const int tid  = threadIdx.x;
    const int wid  = tid >> 5;
    const int lane = tid & 31;
    const int b    = blockIdx.x;

    const float4* __restrict__ base =
        (const float4*)(in + (size_t)b * (N_ROWS * D_COLS));

    // per-lane partial of s: 16 float4 (lane covers columns j*128 + lane*4 .. +3)
    float4 s[16];
#pragma unroll
    for (int j = 0; j < 16; ++j) s[j] = make_float4(0.f, 0.f, 0.f, 0.f);

    double diag_acc = 0.0;

    // warp wid owns rows {wid, wid+16, wid+32, wid+48}; process as 2 interleaved pairs
#pragma unroll
    for (int i = 0; i < 2; ++i) {
        const float4* __restrict__ rowA = base + (wid + i * 32) * (D_COLS / 4);
        const float4* __restrict__ rowB = rowA + 16 * (D_COLS / 4);

        // pass A: squared sums of both rows, 32 independent LDG.128 in flight
        float a0 = 0.f, a1 = 0.f, a2 = 0.f, a3 = 0.f;
        float c0 = 0.f, c1 = 0.f, c2 = 0.f, c3 = 0.f;
#pragma unroll
        for (int j = 0; j < 16; ++j) {
            float4 va = rowA[j * 32 + lane];
            float4 vb = rowB[j * 32 + lane];
            a0 = fmaf(va.x, va.x, a0);
            a1 = fmaf(va.y, va.y, a1);
            a2 = fmaf(va.z, va.z, a2);
            a3 = fmaf(va.w, va.w, a3);
            c0 = fmaf(vb.x, vb.x, c0);
            c1 = fmaf(vb.y, vb.y, c1);
            c2 = fmaf(vb.z, vb.z, c2);
            c3 = fmaf(vb.w, vb.w, c3);
        }
        float sqA = (a0 + a1) + (a2 + a3);
        float sqB = (c0 + c1) + (c2 + c3);
#pragma unroll
        for (int o = 16; o > 0; o >>= 1) {
            sqA += __shfl_xor_sync(0xffffffffu, sqA, o);
            sqB += __shfl_xor_sync(0xffffffffu, sqB, o);
        }

        float invA = 1.0f / fmaxf(sqrtf(sqA), EPSF);
        float invB = 1.0f / fmaxf(sqrtf(sqB), EPSF);

        if (lane == 0) {
            diag_acc += (double)sqA * ((double)invA * (double)invA);
            diag_acc += (double)sqB * ((double)invB * (double)invB);
        }

        // pass B: re-read both rows (L1 hits) and accumulate s
#pragma unroll
        for (int j = 0; j < 16; ++j) {
            float4 va = rowA[j * 32 + lane];
            float4 vb = rowB[j * 32 + lane];
            s[j].x = fmaf(va.x, invA, s[j].x);
            s[j].y = fmaf(va.y, invA, s[j].y);
            s[j].z = fmaf(va.z, invA, s[j].z);
            s[j].w = fmaf(va.w, invA, s[j].w);
            s[j].x = fmaf(vb.x, invB, s[j].x);
            s[j].y = fmaf(vb.y, invB, s[j].y);
            s[j].z = fmaf(vb.z, invB, s[j].z);
            s[j].w = fmaf(vb.w, invB, s[j].w);
        }
    }

    if (lane == 0) dred[wid] = diag_acc;

    // cross-warp reduction of s, in 4 column-chunks of 128 float4 each
    double ssq = 0.0;
#pragma unroll
    for (int c = 0; c < 4; ++c) {
        __syncthreads();
#pragma unroll
        for (int jj = 0; jj < 4; ++jj)
            sbuf[wid][jj * 32 + lane] = s[c * 4 + jj];
        __syncthreads();
        if (tid < 128) {
            float4 tot = sbuf[0][tid];
#pragma unroll
            for (int w = 1; w < NWARP; ++w) {
                float4 p = sbuf[w][tid];
                tot.x += p.x; tot.y += p.y; tot.z += p.z; tot.w += p.w;
            }
            ssq += (double)tot.x * (double)tot.x;
            ssq += (double)tot.y * (double)tot.y;
            ssq += (double)tot.z * (double)tot.z;
            ssq += (double)tot.w * (double)tot.w;
        }
    }

#pragma unroll
    for (int o = 16; o > 0; o >>= 1)
        ssq += __shfl_xor_sync(0xffffffffu, ssq, o);
    if (lane == 0) dred[NWARP + wid] = ssq;
    __syncthreads();

    if (tid == 0) {
        double S = 0.0, Dg = 0.0;
#pragma unroll
        for (int w = 0; w < NWARP; ++w) { Dg += dred[w]; S += dred[NWARP + w]; }
        g_batch_loss[b] = S - Dg;
        __threadfence();
        s_ticket = atomicAdd(&g_done, 1u);
    }
    __syncthreads();

    // last finishing block performs the (deterministic, fixed-order) final mean
    if (s_ticket == B_BATCH - 1) {
        double v = (tid < B_BATCH) ? g_batch_loss[tid] : 0.0;
#pragma unroll
        for (int o = 16; o > 0; o >>= 1)
            v += __shfl_xor_sync(0xffffffffu, v, o);
        if (lane == 0) dred[wid] = v;
        __syncthreads();
        if (tid == 0) {
            double t = 0.0;
#pragma unroll
            for (int w = 0; w < NWARP; ++w) t += dred[w];
            out[0] = (float)(t / (double)B_BATCH);
            g_done = 0;   // self-reset for next graph replay
        }
    }
}

extern "C" void kernel_launch(void* const* d_in, const int* in_sizes, int n_in,
                              void* d_out, int out_size)
{
    (void)in_sizes; (void)n_in; (void)out_size;
    const float* in = (const float*)d_in[0];
    float* out = (float*)d_out;

    loss_fused_kernel<<<B_BATCH, NTHREADS>>>(in, out);
}

// round 3
// speedup vs baseline: 1.1931x; 1.1931x over previous
#include <cuda_runtime.h>

// loss = mean_b( ||sum_n att_n||^2 - sum_n ||att_n||^2 ),  att_n = x_n / max(||x_n||, 1e-12)
// B=128, N=64, D=2048.
// One 1024-thread CTA per batch. Chunked two-phase per 16-row group:
//   phase 1: warp-pair per row -> sumsq -> inv (warp 0 combines halves)
//   phase 2: each warp owns a disjoint 64-column slice of s (float2/lane),
//            accumulates over the group's rows from L1 (128KB group fits L1).
// Final cross-batch mean fused via last-block ticket (fixed-order, deterministic).

#define B_BATCH 128
#define N_ROWS  64
#define D_COLS  2048
#define NTHREADS 1024
#define EPSF    1e-12f

static __device__ double g_batch_loss[B_BATCH];
static __device__ unsigned int g_done = 0;

__global__ void __launch_bounds__(NTHREADS, 1)
loss_fused_kernel(const float* __restrict__ in, float* __restrict__ out)
{
    __shared__ float  partial_sm[32];   // per-warp half-row sumsq
    __shared__ float  inv_sm[16];       // per-row inv norm for current group
    __shared__ double dsm[32];          // block reduce scratch
    __shared__ unsigned int s_ticket;

    const int tid  = threadIdx.x;
    const int wid  = tid >> 5;
    const int lane = tid & 31;
    const int b    = blockIdx.x;

    const float*  base = in + (size_t)b * (N_ROWS * D_COLS);
    const float4* b4   = (const float4*)base;   // 512 float4 per row
    const float2* b2   = (const float2*)base;   // 1024 float2 per row

    // warp wid owns columns [wid*64, wid*64+64) -> per-lane float2 slice
    float2 s = make_float2(0.f, 0.f);
    double diag = 0.0;                  // meaningful on warp 0, lanes 0..15

#pragma unroll
    for (int g = 0; g < 4; ++g) {
        // ---- phase 1: sumsq of 16 rows, 2 warps per row ----
        {
            const int row  = g * 16 + (wid >> 1);
            const int half = wid & 1;
            const float4* __restrict__ rp = b4 + row * 512 + half * 256;

            float a0 = 0.f, a1 = 0.f, a2 = 0.f, a3 = 0.f;
#pragma unroll
            for (int j = 0; j < 8; ++j) {
                float4 v = rp[j * 32 + lane];
                a0 = fmaf(v.x, v.x, a0);
                a1 = fmaf(v.y, v.y, a1);
                a2 = fmaf(v.z, v.z, a2);
                a3 = fmaf(v.w, v.w, a3);
            }
            float sq = (a0 + a1) + (a2 + a3);
#pragma unroll
            for (int o = 16; o > 0; o >>= 1)
                sq += __shfl_xor_sync(0xffffffffu, sq, o);
            if (lane == 0) partial_sm[wid] = sq;
        }
        __syncthreads();

        if (wid == 0 && lane < 16) {
            float p   = partial_sm[2 * lane] + partial_sm[2 * lane + 1];
            float inv = 1.0f / fmaxf(sqrtf(p), EPSF);
            inv_sm[lane] = inv;
            diag += (double)p * ((double)inv * (double)inv);
        }
        __syncthreads();

        // ---- phase 2: accumulate s slice over the 16 rows (L1 hits) ----
        {
            const float2* __restrict__ cp = b2 + (g * 16) * 1024 + wid * 32 + lane;
#pragma unroll
            for (int r = 0; r < 16; ++r) {
                float2 v  = cp[r * 1024];
                float  iv = inv_sm[r];
                s.x = fmaf(v.x, iv, s.x);
                s.y = fmaf(v.y, iv, s.y);
            }
        }
        __syncthreads();   // inv_sm reused next group
    }

    // ---- epilogue: ||s||^2 (slices disjoint -> plain block reduce) ----
    double ssq = (double)s.x * (double)s.x + (double)s.y * (double)s.y;
#pragma unroll
    for (int o = 16; o > 0; o >>= 1)
        ssq += __shfl_xor_sync(0xffffffffu, ssq, o);
    if (lane == 0) dsm[wid] = ssq;

    // diag: warp 0 lanes 0..15 hold partials (others 0)
#pragma unroll
    for (int o = 16; o > 0; o >>= 1)
        diag += __shfl_xor_sync(0xffffffffu, diag, o);
    __syncthreads();

    if (tid == 0) {
        double S = 0.0;
#pragma unroll
        for (int w = 0; w < 32; ++w) S += dsm[w];
        g_batch_loss[b] = S - diag;
        __threadfence();
        s_ticket = atomicAdd(&g_done, 1u);
    }
    __syncthreads();

    // last finishing block: deterministic fixed-order mean over batches
    if (s_ticket == B_BATCH - 1) {
        double v = (tid < B_BATCH) ? g_batch_loss[tid] : 0.0;
#pragma unroll
        for (int o = 16; o > 0; o >>= 1)
            v += __shfl_xor_sync(0xffffffffu, v, o);
        if (lane == 0) dsm[wid] = v;
        __syncthreads();
        if (tid == 0) {
            double t = 0.0;
#pragma unroll
            for (int w = 0; w < 4; ++w) t += dsm[w];
            out[0] = (float)(t / (double)B_BATCH);
            g_done = 0;   // self-reset for graph replay
        }
    }
}

extern "C" void kernel_launch(void* const* d_in, const int* in_sizes, int n_in,
                              void* d_out, int out_size)
{
    (void)in_sizes; (void)n_in; (void)out_size;
    const float* in = (const float*)d_in[0];
    float* out = (float*)d_out;

    loss_fused_kernel<<<B_BATCH, NTHREADS>>>(in, out);
}

// round 7
// speedup vs baseline: 1.6794x; 1.4076x over previous
#include <cuda_runtime.h>

// loss = mean_b( ||sum_n att_n||^2 - sum_n ||att_n||^2 ),  att_n = x_n / max(||x_n||, 1e-12)
// B=128, N=64, D=2048.
// 128 CTAs x 256 threads (8 warps). Warp-independent streaming: warp w owns
// rows {w, w+8, ...}; each row is held in registers (16 float4) between the
// sumsq pass and the scaled accumulation into the warp's full-width s partial
// (16 float4). No block barriers until the epilogue. Final cross-batch mean
// fused via last-block ticket (fixed-order, deterministic, self-resetting).

#define B_BATCH 128
#define N_ROWS  64
#define D_COLS  2048          // 512 float4 per row
#define NWARP   8
#define NTHREADS 256
#define EPSF    1e-12f

static __device__ double g_batch_loss[B_BATCH];
static __device__ unsigned int g_done = 0;

__global__ void __launch_bounds__(NTHREADS, 1)
loss_fused_kernel(const float* __restrict__ in, float* __restrict__ out)
{
    __shared__ float4 sbuf[NWARP][128];   // 16 KB publish area (per column chunk)
    __shared__ double dsm[2 * NWARP];     // [0..7]=ssq per warp, [8..15]=diag per warp
    __shared__ unsigned int s_ticket;

    const int tid  = threadIdx.x;
    const int wid  = tid >> 5;
    const int lane = tid & 31;
    const int b    = blockIdx.x;

    const float4* __restrict__ base =
        (const float4*)(in + (size_t)b * (N_ROWS * D_COLS));

    // warp-wide s partial over all 2048 columns: lane covers cols (j*32+lane)*4..+3
    float4 s[16];
#pragma unroll
    for (int j = 0; j < 16; ++j) s[j] = make_float4(0.f, 0.f, 0.f, 0.f);

    double diag = 0.0;   // lane 0 only

    // warp wid owns rows wid, wid+8, ..., wid+56 — fully independent, no barriers
#pragma unroll
    for (int k = 0; k < 8; ++k) {
        const float4* __restrict__ row = base + (wid + k * NWARP) * (D_COLS / 4);

        // stream the row into registers; interleave sumsq FMAs so loads retire
        // in order and the reduce tail is short
        float4 d[16];
        float a0 = 0.f, a1 = 0.f, a2 = 0.f, a3 = 0.f;
#pragma unroll
        for (int j = 0; j < 16; ++j) {
            d[j] = row[j * 32 + lane];
            a0 = fmaf(d[j].x, d[j].x, a0);
            a1 = fmaf(d[j].y, d[j].y, a1);
            a2 = fmaf(d[j].z, d[j].z, a2);
            a3 = fmaf(d[j].w, d[j].w, a3);
        }
        float sq = (a0 + a1) + (a2 + a3);
#pragma unroll
        for (int o = 16; o > 0; o >>= 1)
            sq += __shfl_xor_sync(0xffffffffu, sq, o);

        float inv = 1.0f / fmaxf(sqrtf(sq), EPSF);

        if (lane == 0)
            diag += (double)sq * ((double)inv * (double)inv);

        // scaled accumulate from registers (no memory traffic)
#pragma unroll
        for (int j = 0; j < 16; ++j) {
            s[j].x = fmaf(d[j].x, inv, s[j].x);
            s[j].y = fmaf(d[j].y, inv, s[j].y);
            s[j].z = fmaf(d[j].z, inv, s[j].z);
            s[j].w = fmaf(d[j].w, inv, s[j].w);
        }
    }

    if (lane == 0) dsm[NWARP + wid] = diag;

    // ---- epilogue: reduce s across the 8 warps in 4 column chunks ----
    double ssq = 0.0;
#pragma unroll
    for (int c = 0; c < 4; ++c) {
        __syncthreads();
#pragma unroll
        for (int jj = 0; jj < 4; ++jj)
            sbuf[wid][jj * 32 + lane] = s[c * 4 + jj];
        __syncthreads();
        if (tid < 128) {
            float4 tot = sbuf[0][tid];
#pragma unroll
            for (int w = 1; w < NWARP; ++w) {
                float4 p = sbuf[w][tid];
                tot.x += p.x; tot.y += p.y; tot.z += p.z; tot.w += p.w;
            }
            ssq += (double)tot.x * (double)tot.x;
            ssq += (double)tot.y * (double)tot.y;
            ssq += (double)tot.z * (double)tot.z;
            ssq += (double)tot.w * (double)tot.w;
        }
    }

    // block-reduce ssq (upper 128 threads contribute 0)
#pragma unroll
    for (int o = 16; o > 0; o >>= 1)
        ssq += __shfl_xor_sync(0xffffffffu, ssq, o);
    if (lane == 0) dsm[wid] = ssq;
    __syncthreads();

    if (tid == 0) {
        double S = 0.0, Dg = 0.0;
#pragma unroll
        for (int w = 0; w < NWARP; ++w) { S += dsm[w]; Dg += dsm[NWARP + w]; }
        g_batch_loss[b] = S - Dg;
        __threadfence();
        s_ticket = atomicAdd(&g_done, 1u);
    }
    __syncthreads();

    // last finishing block: deterministic fixed-order mean over batches
    if (s_ticket == B_BATCH - 1) {
        double v = (tid < B_BATCH) ? g_batch_loss[tid] : 0.0;
#pragma unroll
        for (int o = 16; o > 0; o >>= 1)
            v += __shfl_xor_sync(0xffffffffu, v, o);
        if (lane == 0) dsm[wid] = v;
        __syncthreads();
        if (tid == 0) {
            double t = 0.0;
#pragma unroll
            for (int w = 0; w < 4; ++w) t += dsm[w];   // batches live in warps 0..3
            out[0] = (float)(t / (double)B_BATCH);
            g_done = 0;   // self-reset for graph replay
        }
    }
}

extern "C" void kernel_launch(void* const* d_in, const int* in_sizes, int n_in,
                              void* d_out, int out_size)
{
    (void)in_sizes; (void)n_in; (void)out_size;
    const float* in = (const float*)d_in[0];
    float* out = (float*)d_out;

    loss_fused_kernel<<<B_BATCH, NTHREADS>>>(in, out);
}